// round 16
// baseline (speedup 1.0000x reference)
#include <cuda_runtime.h>
#include <cstdint>
#include <math.h>

typedef unsigned long long ull;

// ---------------- problem constants ----------------
#define TSTEPS 512
#define BATCH  256
#define DIN    128
#define HID    256
#define NPROTO 128
#define DH     384   // DIN + HID

// ---------------- decomposition ----------------
#define CSZ 4                 // CTAs per cluster
#define NCLUST (BATCH / 8)    // 32 clusters
#define RPC 8                 // batch rows per cluster
#define PPC 32                // prototypes per CTA
#define NCOL 256              // gate columns per CTA (4 gates x 64 hidden)
#define NTHR 512              // 16 warps, 4 per SMSP
#define NWARP 16
#define DPW 24                // dims per warp in phase-1 dot (DH / NWARP)

#define L2E 1.4426950408889634f

// ---------------- smem layout (float offsets) ----------------
#define CSTR 388                      // comb row stride (384 + pad, 16B aligned)
#define OFF_W    0
#define SZ_W     (NPROTO * NCOL)      // 32768 (128 KB)
#define OFF_COMB (OFF_W + SZ_W)       // 32768 (byte 131072, 16B aligned)
#define SZ_COMB  (RPC * CSTR)         // 3104
#define OFF_PART (OFF_COMB + SZ_COMB) // 35872 ; part[s][r][p], stride 260
#define PSTRIDE  260
#define SZ_PART  (NWARP * PSTRIDE)    // 4160
#define OFF_KT   (OFF_PART + SZ_PART) // 40032 (byte 160128, 16B aligned)
#define KTSTR    12                   // floats per proto (8 rows + pad to 48B)
#define SZ_KT    (NPROTO * KTSTR)     // 1536
// G quadrant partials: 4 quarters x 128 colpairs x 9 u64 (stride-9 conflict-free)
#define OFF_GQ   (OFF_KT + SZ_KT)     // 41568 (byte 166272, 16B aligned)
#define GQ_QUARTER_U64 1152           // 128*9
#define SZ_GQ    (4 * GQ_QUARTER_U64 * 2)  // 9216 floats
#define OFF_CSQ  (OFF_GQ + SZ_GQ)     // 50784 ; |c|^2 per row (8 + pad)
#define SZ_CSQ   16
#define OFF_PSQ  (OFF_CSQ + SZ_CSQ)   // 50800 ; L2E*|p|^2 per proto (128)
#define SZ_PSQ   NPROTO
#define OFF_B    (OFF_PSQ + SZ_PSQ)   // 50928
#define SZ_B     NCOL
#define SMEM_FLOATS (OFF_B + SZ_B)    // 51184
#define SMEM_BYTES  (SMEM_FLOATS * 4) // 204736 B (< 227 KB opt-in)

// ---------------- helpers ----------------
__device__ __forceinline__ ull ffma2(ull a, ull b, ull c) {
    ull d;
    asm("fma.rn.f32x2 %0, %1, %2, %3;" : "=l"(d) : "l"(a), "l"(b), "l"(c));
    return d;
}
__device__ __forceinline__ ull fadd2(ull a, ull b) {
    ull d;
    asm("add.rn.f32x2 %0, %1, %2;" : "=l"(d) : "l"(a), "l"(b));
    return d;
}
__device__ __forceinline__ void lds_v2u64(ull& a, ull& b, uint32_t addr) {
    asm volatile("ld.shared.v2.u64 {%0, %1}, [%2];"
                 : "=l"(a), "=l"(b) : "r"(addr));
}
__device__ __forceinline__ void lds_v2f32(float& a, float& b, uint32_t addr) {
    asm volatile("ld.shared.v2.f32 {%0, %1}, [%2];"
                 : "=f"(a), "=f"(b) : "r"(addr));
}
__device__ __forceinline__ ull lds_u64(uint32_t addr) {
    ull a;
    asm volatile("ld.shared.b64 %0, [%1];" : "=l"(a) : "r"(addr));
    return a;
}
__device__ __forceinline__ void sts_u64(uint32_t addr, ull v) {
    asm volatile("st.shared.b64 [%0], %1;" :: "r"(addr), "l"(v) : "memory");
}
__device__ __forceinline__ uint32_t mapa_u32(uint32_t saddr, uint32_t rank) {
    uint32_t ra;
    asm("mapa.shared::cluster.u32 %0, %1, %2;" : "=r"(ra) : "r"(saddr), "r"(rank));
    return ra;
}
__device__ __forceinline__ void st_cluster_pre(uint32_t ra, float v) {
    asm volatile("st.shared::cluster.f32 [%0], %1;" :: "r"(ra), "f"(v) : "memory");
}
__device__ __forceinline__ void cluster_arrive() {
    asm volatile("barrier.cluster.arrive.aligned;" ::: "memory");
}
__device__ __forceinline__ void cluster_wait() {
    asm volatile("barrier.cluster.wait.aligned;" ::: "memory");
}
__device__ __forceinline__ float fex2(float x) {
    float r; asm("ex2.approx.f32 %0, %1;" : "=f"(r) : "f"(x)); return r;
}
__device__ __forceinline__ float frcp(float x) {
    float r; asm("rcp.approx.f32 %0, %1;" : "=f"(r) : "f"(x)); return r;
}
// sigmoid(x) = 1 / (1 + 2^(-x*log2 e))     (~1e-7 accuracy, 2 MUFU)
__device__ __forceinline__ float fsigm(float x) {
    return frcp(1.0f + fex2(-L2E * x));
}
// tanh(x) = 2*sigmoid(2x) - 1
__device__ __forceinline__ float ftanh(float x) {
    return fmaf(2.0f, frcp(1.0f + fex2(-2.0f * L2E * x)), -1.0f);
}
__device__ __forceinline__ ull splat2(float v) {
    ull d;
    asm("mov.b64 %0, {%1, %1};" : "=l"(d) : "f"(v));
    return d;
}
__device__ __forceinline__ void unpack2(float& a, float& b, ull v) {
    asm("mov.b64 {%0, %1}, %2;" : "=f"(a), "=f"(b) : "l"(v));
}

// ---------------- kernel ----------------
__global__ void __cluster_dims__(CSZ, 1, 1) __launch_bounds__(NTHR, 1)
qlstm_kernel(const float* __restrict__ x,      // [T, B, DIN]
             const float* __restrict__ protos, // [P, DH]
             const float* __restrict__ Wf, const float* __restrict__ bf,
             const float* __restrict__ Wi, const float* __restrict__ bi,
             const float* __restrict__ Wg, const float* __restrict__ bg,
             const float* __restrict__ Wo, const float* __restrict__ bo,
             float* __restrict__ out, int out_size)
{
    extern __shared__ float sm[];
    const uint32_t sb = (uint32_t)__cvta_generic_to_shared(sm);
    const int tid = threadIdx.x;
    const int w = tid >> 5;   // warp id 0..15
    const int l = tid & 31;   // lane

    uint32_t q;  // cluster rank 0..3
    asm("mov.u32 %0, %%cluster_ctarank;" : "=r"(q));
    const int cl = blockIdx.x / CSZ;
    const int row0 = cl * RPC;      // first global batch row of this cluster

    // ---------------- one-time init ----------------
    const float* Wp[4] = {Wf, Wi, Wg, Wo};
    const float* bp[4] = {bf, bi, bg, bo};

    // Wsm[p][c] with c = gate*64 + u_local ; Wsm[p][c] = W_gate[q*64+u][p]
    for (int i = tid; i < SZ_W; i += NTHR) {
        int p = i >> 8;
        int c = i & 255;
        int g = c >> 6;
        int u = c & 63;
        sm[OFF_W + i] = Wp[g][(q * 64 + u) * NPROTO + p];
    }
    if (tid < NCOL) sm[OFF_B + tid] = bp[tid >> 6][q * 64 + (tid & 63)];
    for (int i = tid; i < SZ_COMB; i += NTHR) sm[OFF_COMB + i] = 0.0f;  // h0 = 0
    __syncthreads();

    // x[0] into comb x-region: thread -> row tid>>6, dims 2*(tid&63)
    {
        const int r = tid >> 6, dd = tid & 63;
        const float2 xv = *(const float2*)&x[(size_t)(row0 + r) * DIN + 2 * dd];
        *(float2*)&sm[OFF_COMB + r * CSTR + 2 * dd] = xv;
    }

    // prototypes in registers: thread (slice s = w, proto = l) holds
    // proto[q*32 + l][24*w .. 24*w+23] as 12 packed f32x2
    ull pr[12];
    {
        const float* prow = protos + (size_t)(q * PPC + l) * DH + w * DPW;
        #pragma unroll
        for (int j = 0; j < 12; j++) {
            float2 v = *(const float2*)&prow[2 * j];
            asm("mov.b64 %0, {%1, %2};" : "=l"(pr[j]) : "f"(v.x), "f"(v.y));
        }
    }
    // |p|^2 partial for this slice -> PART scratch
    {
        ull a0 = 0, a1 = 0;
        #pragma unroll
        for (int j = 0; j < 12; j += 2) {
            a0 = ffma2(pr[j],     pr[j],     a0);
            a1 = ffma2(pr[j + 1], pr[j + 1], a1);
        }
        float lo, hi;
        unpack2(lo, hi, fadd2(a0, a1));
        sm[OFF_PART + w * PSTRIDE + l] = lo + hi;
    }
    __syncthreads();
    // reduce |p|^2 over slices, scale by L2E, DSMEM-share to all CTAs
    if (tid < PPC) {
        float s = 0.0f;
        #pragma unroll
        for (int ww = 0; ww < NWARP; ww++) s += sm[OFF_PART + ww * PSTRIDE + tid];
        s *= L2E;
        const uint32_t pa = sb + (uint32_t)(OFF_PSQ + q * PPC + tid) * 4;
        #pragma unroll
        for (uint32_t rk = 0; rk < CSZ; rk++) st_cluster_pre(mapa_u32(pa, rk), s);
    }
    cluster_arrive();
    cluster_wait();

    const uint32_t comb_b = sb + OFF_COMB * 4;
    const uint32_t kt_b   = sb + OFF_KT * 4;
    const uint32_t gq_b   = sb + OFF_GQ * 4;

    float cc = 0.0f;  // persistent cell state (this thread's unit)
    float hh = 0.0f;

    // fixed per-thread roles
    const int r3 = tid >> 6;            // phase-3 row 0..7
    const int u3 = tid & 63;            // phase-3 hidden unit 0..63
    const int qt = w >> 2;              // phase-2 K-quarter 0..3
    const int cp = ((w & 3) << 5) + l;  // phase-2 column pair 0..127
    const int c2 = 2 * cp;              // first column of the pair

    // hoisted DSMEM addresses (loop-invariant mapa)
    uint32_t ka[CSZ], ha[CSZ];
    {
        // finalize role (warps 0-7): proto pf = l, row rf = w
        const int pg = q * PPC + l;
        const uint32_t kaddr = kt_b + (uint32_t)(pg * KTSTR + (w & 7)) * 4;
        const uint32_t haddr = comb_b + (uint32_t)(r3 * CSTR + DIN + q * 64 + u3) * 4;
        #pragma unroll
        for (uint32_t rk = 0; rk < CSZ; rk++) {
            ka[rk] = mapa_u32(kaddr, rk);
            ha[rk] = mapa_u32(haddr, rk);
        }
    }

    // phase-2 fixed addresses
    const uint32_t kb2 = kt_b + (uint32_t)qt * (32 * 48);          // k base for quarter
    const uint32_t wb2 = sb + (uint32_t)(OFF_W + qt * 32 * NCOL + c2) * 4;
    const uint32_t gq_self = gq_b + (uint32_t)((qt * GQ_QUARTER_U64 + cp * 9) * 8);

    // phase-3 fixed addresses: gate g partial sum base
    // addr(g, qt) = gq_b + (qt*1152 + (g*32 + (u3>>1))*9 + (u3&1)*4 + (r3>>1)) * 8
    const int rsel = r3 & 1;
    const uint32_t gq_rd = gq_b +
        (uint32_t)((((u3 >> 1) * 9) + (u3 & 1) * 4 + (r3 >> 1)) * 8);

    // output pointer (bumped per step)
    float* outp = out + ((size_t)(row0 + r3) * HID + q * 64 + u3);

    for (int t = 0; t < TSTEPS; t++) {
        // ---------- phase 1a (warps 8-15): |c|^2 per row ----------
        if (w >= 8) {
            const int r = w - 8;
            const uint32_t a = comb_b + (uint32_t)(r * CSTR * 4) + (uint32_t)l * 16;
            ull a0 = 0, a1 = 0;
            #pragma unroll
            for (int ch = 0; ch < 3; ch++) {
                ull c01, c23;
                lds_v2u64(c01, c23, a + ch * 512);
                a0 = ffma2(c01, c01, a0);
                a1 = ffma2(c23, c23, a1);
            }
            float lo, hi;
            unpack2(lo, hi, fadd2(a0, a1));
            float s = lo + hi;
            s += __shfl_xor_sync(0xFFFFFFFFu, s, 16);
            s += __shfl_xor_sync(0xFFFFFFFFu, s, 8);
            s += __shfl_xor_sync(0xFFFFFFFFu, s, 4);
            s += __shfl_xor_sync(0xFFFFFFFFu, s, 2);
            s += __shfl_xor_sync(0xFFFFFFFFu, s, 1);
            if (l == 0) sm[OFF_CSQ + r] = s;
        }

        // ---------- phase 1b: dot products c.p (16-way split-K, protos in regs) ----------
        {
            const uint32_t cslice = comb_b + w * (DPW * 4);  // this warp's 24-dim slice
            #pragma unroll 1
            for (int r = 0; r < RPC; r++) {
                ull a0 = 0, a1 = 0;
                const uint32_t a = cslice + r * (CSTR * 4);
                #pragma unroll
                for (int jv = 0; jv < 6; jv++) {
                    ull c01, c23;
                    lds_v2u64(c01, c23, a + jv * 16);        // broadcast across warp
                    a0 = ffma2(pr[2 * jv],     c01, a0);
                    a1 = ffma2(pr[2 * jv + 1], c23, a1);
                }
                float lo, hi;
                unpack2(lo, hi, fadd2(a0, a1));
                sm[OFF_PART + w * PSTRIDE + r * 32 + l] = lo + hi;  // conflict-free
            }
        }
        __syncthreads();

        // ---------- prefetch x_{t+1} (consumed in phase 3) ----------
        float2 xv;
        {
            const int tn = (t + 1 < TSTEPS) ? t + 1 : t;
            xv = *(const float2*)&x[((size_t)tn * BATCH + row0 + r3) * DIN + 2 * u3];
        }

        // ---------- finalize k = exp(2*dot - |c|^2 - |p|^2), DSMEM to all CTAs ----------
        if (w < 8) {
            const int pf = l;          // local proto 0..31 (lane)
            const int rf = w;          // row 0..7
            float s0 = 0.0f, s1 = 0.0f;
            #pragma unroll
            for (int s = 0; s < 16; s += 2) {
                s0 += sm[OFF_PART + s * PSTRIDE + rf * 32 + pf];
                s1 += sm[OFF_PART + (s + 1) * PSTRIDE + rf * 32 + pf];
            }
            const float dot = s0 + s1;
            const float t1 = fmaf(L2E, sm[OFF_CSQ + rf], sm[OFF_PSQ + q * PPC + pf]);
            const float kv = fex2(fmaf(2.0f * L2E, dot, -t1));
            #pragma unroll
            for (uint32_t rk = 0; rk < CSZ; rk++) st_cluster_pre(ka[rk], kv);
        }
        __syncthreads();  // local kt quarter fully written (all 8 finalize warps)

        cluster_arrive();

        // ---------- phase 2: gate GEMM quarter (2 cols/thread, 32 protos) ----------
        // Warps whose quarter == own rank need only locally-produced k rows:
        // run them between arrive and wait to hide cluster latency.
        #define GEMM_QUARTER()                                                    \
        {                                                                         \
            ull ac0 = 0, ac1 = 0, ac2 = 0, ac3 = 0;                               \
            ull ad0 = 0, ad1 = 0, ad2 = 0, ad3 = 0;                               \
            _Pragma("unroll 8")                                                   \
            for (int p = 0; p < 32; p++) {                                        \
                ull k01, k23, k45, k67;                                           \
                lds_v2u64(k01, k23, kb2 + p * 48);                                \
                lds_v2u64(k45, k67, kb2 + p * 48 + 16);                           \
                float w0, w1;                                                     \
                lds_v2f32(w0, w1, wb2 + (uint32_t)p * (NCOL * 4));                \
                const ull ww0 = splat2(w0);                                       \
                const ull ww1 = splat2(w1);                                       \
                ac0 = ffma2(k01, ww0, ac0);                                       \
                ac1 = ffma2(k23, ww0, ac1);                                       \
                ac2 = ffma2(k45, ww0, ac2);                                       \
                ac3 = ffma2(k67, ww0, ac3);                                       \
                ad0 = ffma2(k01, ww1, ad0);                                       \
                ad1 = ffma2(k23, ww1, ad1);                                       \
                ad2 = ffma2(k45, ww1, ad2);                                       \
                ad3 = ffma2(k67, ww1, ad3);                                       \
            }                                                                     \
            sts_u64(gq_self,      ac0);                                           \
            sts_u64(gq_self + 8,  ac1);                                           \
            sts_u64(gq_self + 16, ac2);                                           \
            sts_u64(gq_self + 24, ac3);                                           \
            sts_u64(gq_self + 32, ad0);                                           \
            sts_u64(gq_self + 40, ad1);                                           \
            sts_u64(gq_self + 48, ad2);                                           \
            sts_u64(gq_self + 56, ad3);                                           \
        }

        if (qt == (int)q) GEMM_QUARTER();
        cluster_wait();   // sync #1: full k in every CTA
        if (qt != (int)q) GEMM_QUARTER();
        __syncthreads();

        // ---------- phase 3: reduce 4 quadrants, LSTM update, h broadcast ----------
        {
            float gv4[4];
            #pragma unroll
            for (int g = 0; g < 4; g++) {
                const uint32_t b = gq_rd + (uint32_t)(g * (32 * 9 * 8));
                ull v = lds_u64(b);
                v = fadd2(v, lds_u64(b + GQ_QUARTER_U64 * 8));
                v = fadd2(v, lds_u64(b + 2 * GQ_QUARTER_U64 * 8));
                v = fadd2(v, lds_u64(b + 3 * GQ_QUARTER_U64 * 8));
                float lo, hi;
                unpack2(lo, hi, v);
                gv4[g] = (rsel ? hi : lo) + sm[OFF_B + g * 64 + u3];
            }
            const float fv = fsigm(gv4[0]);
            const float iv = fsigm(gv4[1]);
            const float gv = ftanh(gv4[2]);
            const float ov = fsigm(gv4[3]);
            cc = fv * cc + iv * gv;
            const float h = ov * ftanh(cc);
            hh = h;
            *outp = h;
            outp += (size_t)BATCH * HID;
            #pragma unroll
            for (uint32_t rk = 0; rk < CSZ; rk++) st_cluster_pre(ha[rk], h);
        }
        cluster_arrive();
        // install prefetched x_{t+1} (local-only region of comb) under cluster latency
        *(float2*)&sm[OFF_COMB + r3 * CSTR + 2 * u3] = xv;
        cluster_wait();   // sync #2: comb (x, h) ready for next step
    }

    // ---------------- epilogue: hx, cx ----------------
    {
        const size_t base = (size_t)TSTEPS * BATCH * HID;
        if ((size_t)out_size >= base + 2 * (size_t)BATCH * HID) {
            const size_t idx = (size_t)(row0 + r3) * HID + q * 64 + u3;
            out[base + idx] = hh;
            out[base + (size_t)BATCH * HID + idx] = cc;
        }
    }
}

// ---------------- launch ----------------
extern "C" void kernel_launch(void* const* d_in, const int* in_sizes, int n_in,
                              void* d_out, int out_size) {
    const float* x      = (const float*)d_in[0];
    const float* protos = (const float*)d_in[1];
    const float* Wf     = (const float*)d_in[2];
    const float* bf     = (const float*)d_in[3];
    const float* Wi     = (const float*)d_in[4];
    const float* bi     = (const float*)d_in[5];
    const float* Wg     = (const float*)d_in[6];
    const float* bg     = (const float*)d_in[7];
    const float* Wo     = (const float*)d_in[8];
    const float* bo     = (const float*)d_in[9];

    cudaFuncSetAttribute(qlstm_kernel,
                         cudaFuncAttributeMaxDynamicSharedMemorySize, SMEM_BYTES);

    qlstm_kernel<<<NCLUST * CSZ, NTHR, SMEM_BYTES>>>(
        x, protos, Wf, bf, Wi, bi, Wg, bg, Wo, bo,
        (float*)d_out, out_size);
}

// round 17
// speedup vs baseline: 1.0625x; 1.0625x over previous
#include <cuda_runtime.h>
#include <cstdint>
#include <math.h>

typedef unsigned long long ull;

// ---------------- problem constants ----------------
#define TSTEPS 512
#define BATCH  256
#define DIN    128
#define HID    256
#define NPROTO 128
#define DH     384   // DIN + HID

// ---------------- decomposition ----------------
#define CSZ 4                 // CTAs per cluster
#define NCLUST (BATCH / 8)    // 32 clusters
#define RPC 8                 // batch rows per cluster
#define PPC 32                // prototypes per CTA
#define NCOL 256              // gate columns per CTA (4 gates x 64 hidden)
#define NTHR 512              // 16 warps, 4 per SMSP
#define NWARP 16
#define DPW 24                // dims per warp in phase-1 dot (DH / NWARP)

#define L2E 1.4426950408889634f

// ---------------- smem layout (float offsets) ----------------
#define CSTR 388                      // comb row stride (384 + pad, 16B aligned)
#define OFF_W    0
#define SZ_W     (NPROTO * NCOL)      // 32768 (128 KB)
#define OFF_COMB (OFF_W + SZ_W)       // 32768 (byte 131072, 16B aligned)
#define SZ_COMB  (RPC * CSTR)         // 3104
#define OFF_PART (OFF_COMB + SZ_COMB) // 35872 ; part[s][r][p], stride 260
#define PSTRIDE  260
#define SZ_PART  (NWARP * PSTRIDE)    // 4160
#define OFF_KT   (OFF_PART + SZ_PART) // 40032 (byte 160128, 16B aligned)
#define KTSTR    12                   // floats per proto (8 rows + pad to 48B)
#define SZ_KT    (NPROTO * KTSTR)     // 1536
// phase-2 partials: 3 quarter-regions x 128 colpairs x 9 u64 (stride-9 conflict-free)
#define OFF_GP   (OFF_KT + SZ_KT)     // 41568 (byte 166272, 16B aligned)
#define GPQ_U64  1152                 // u64 per quarter region (128*9)
#define SZ_GP    (3 * GPQ_U64 * 2)    // 6912 floats
#define OFF_G    (OFF_GP + SZ_GP)     // 48480 ; G[r][c], stride 260
#define GSTR     260
#define SZ_G     (RPC * GSTR)         // 2080
#define OFF_B    (OFF_G + SZ_G)       // 50560
#define SZ_B     NCOL
#define OFF_CSQ  (OFF_B + SZ_B)       // 50816 ; |c|^2 per row (8 + pad)
#define SZ_CSQ   16
#define OFF_PSQ  (OFF_CSQ + SZ_CSQ)   // 50832 ; L2E*|p|^2 per proto (128)
#define SZ_PSQ   NPROTO
#define SMEM_FLOATS (OFF_PSQ + SZ_PSQ)   // 50960
#define SMEM_BYTES  (SMEM_FLOATS * 4)    // 203840 B (< 227 KB opt-in)

// ---------------- helpers ----------------
__device__ __forceinline__ ull ffma2(ull a, ull b, ull c) {
    ull d;
    asm("fma.rn.f32x2 %0, %1, %2, %3;" : "=l"(d) : "l"(a), "l"(b), "l"(c));
    return d;
}
__device__ __forceinline__ ull fadd2(ull a, ull b) {
    ull d;
    asm("add.rn.f32x2 %0, %1, %2;" : "=l"(d) : "l"(a), "l"(b));
    return d;
}
__device__ __forceinline__ void lds_v2u64(ull& a, ull& b, uint32_t addr) {
    asm volatile("ld.shared.v2.u64 {%0, %1}, [%2];"
                 : "=l"(a), "=l"(b) : "r"(addr));
}
__device__ __forceinline__ void lds_v2f32(float& a, float& b, uint32_t addr) {
    asm volatile("ld.shared.v2.f32 {%0, %1}, [%2];"
                 : "=f"(a), "=f"(b) : "r"(addr));
}
__device__ __forceinline__ ull lds_u64(uint32_t addr) {
    ull a;
    asm volatile("ld.shared.b64 %0, [%1];" : "=l"(a) : "r"(addr));
    return a;
}
__device__ __forceinline__ void sts_u64(uint32_t addr, ull v) {
    asm volatile("st.shared.b64 [%0], %1;" :: "r"(addr), "l"(v) : "memory");
}
__device__ __forceinline__ uint32_t mapa_u32(uint32_t saddr, uint32_t rank) {
    uint32_t ra;
    asm("mapa.shared::cluster.u32 %0, %1, %2;" : "=r"(ra) : "r"(saddr), "r"(rank));
    return ra;
}
__device__ __forceinline__ void st_cluster_pre(uint32_t ra, float v) {
    asm volatile("st.shared::cluster.f32 [%0], %1;" :: "r"(ra), "f"(v) : "memory");
}
__device__ __forceinline__ void cluster_arrive() {
    asm volatile("barrier.cluster.arrive.aligned;" ::: "memory");
}
__device__ __forceinline__ void cluster_wait() {
    asm volatile("barrier.cluster.wait.aligned;" ::: "memory");
}
__device__ __forceinline__ float fex2(float x) {
    float r; asm("ex2.approx.f32 %0, %1;" : "=f"(r) : "f"(x)); return r;
}
__device__ __forceinline__ float frcp(float x) {
    float r; asm("rcp.approx.f32 %0, %1;" : "=f"(r) : "f"(x)); return r;
}
// sigmoid(x) = 1 / (1 + 2^(-x*log2 e))     (~1e-7 accuracy, 2 MUFU)
__device__ __forceinline__ float fsigm(float x) {
    return frcp(1.0f + fex2(-L2E * x));
}
// tanh(x) = 2*sigmoid(2x) - 1
__device__ __forceinline__ float ftanh(float x) {
    return fmaf(2.0f, frcp(1.0f + fex2(-2.0f * L2E * x)), -1.0f);
}
__device__ __forceinline__ ull splat2(float v) {
    ull d;
    asm("mov.b64 %0, {%1, %1};" : "=l"(d) : "f"(v));
    return d;
}
__device__ __forceinline__ void unpack2(float& a, float& b, ull v) {
    asm("mov.b64 {%0, %1}, %2;" : "=f"(a), "=f"(b) : "l"(v));
}

// ---------------- kernel ----------------
__global__ void __cluster_dims__(CSZ, 1, 1) __launch_bounds__(NTHR, 1)
qlstm_kernel(const float* __restrict__ x,      // [T, B, DIN]
             const float* __restrict__ protos, // [P, DH]
             const float* __restrict__ Wf, const float* __restrict__ bf,
             const float* __restrict__ Wi, const float* __restrict__ bi,
             const float* __restrict__ Wg, const float* __restrict__ bg,
             const float* __restrict__ Wo, const float* __restrict__ bo,
             float* __restrict__ out, int out_size)
{
    extern __shared__ float sm[];
    const uint32_t sb = (uint32_t)__cvta_generic_to_shared(sm);
    const int tid = threadIdx.x;
    const int w = tid >> 5;   // warp id 0..15
    const int l = tid & 31;   // lane

    uint32_t q;  // cluster rank 0..3
    asm("mov.u32 %0, %%cluster_ctarank;" : "=r"(q));
    const int cl = blockIdx.x / CSZ;
    const int row0 = cl * RPC;      // first global batch row of this cluster

    // ---------------- one-time init ----------------
    const float* Wp[4] = {Wf, Wi, Wg, Wo};
    const float* bp[4] = {bf, bi, bg, bo};

    // Wsm[p][c] with c = gate*64 + u_local ; Wsm[p][c] = W_gate[q*64+u][p]
    for (int i = tid; i < SZ_W; i += NTHR) {
        int p = i >> 8;
        int c = i & 255;
        int g = c >> 6;
        int u = c & 63;
        sm[OFF_W + i] = Wp[g][(q * 64 + u) * NPROTO + p];
    }
    if (tid < NCOL) sm[OFF_B + tid] = bp[tid >> 6][q * 64 + (tid & 63)];
    for (int i = tid; i < SZ_COMB; i += NTHR) sm[OFF_COMB + i] = 0.0f;  // h0 = 0
    __syncthreads();

    // x[0] into comb x-region: thread -> row tid>>6, dims 2*(tid&63)
    {
        const int r = tid >> 6, dd = tid & 63;
        const float2 xv = *(const float2*)&x[(size_t)(row0 + r) * DIN + 2 * dd];
        *(float2*)&sm[OFF_COMB + r * CSTR + 2 * dd] = xv;
    }

    // prototypes in registers: thread (slice s = w, proto = l) holds
    // proto[q*32 + l][24*w .. 24*w+23] as 12 packed f32x2
    ull pr[12];
    {
        const float* prow = protos + (size_t)(q * PPC + l) * DH + w * DPW;
        #pragma unroll
        for (int j = 0; j < 12; j++) {
            float2 v = *(const float2*)&prow[2 * j];
            asm("mov.b64 %0, {%1, %2};" : "=l"(pr[j]) : "f"(v.x), "f"(v.y));
        }
    }
    // |p|^2 partial for this slice -> PART scratch
    {
        ull a0 = 0, a1 = 0;
        #pragma unroll
        for (int j = 0; j < 12; j += 2) {
            a0 = ffma2(pr[j],     pr[j],     a0);
            a1 = ffma2(pr[j + 1], pr[j + 1], a1);
        }
        float lo, hi;
        unpack2(lo, hi, fadd2(a0, a1));
        sm[OFF_PART + w * PSTRIDE + l] = lo + hi;
    }
    __syncthreads();
    // reduce |p|^2 over slices, scale by L2E, DSMEM-share to all CTAs
    if (tid < PPC) {
        float s = 0.0f;
        #pragma unroll
        for (int ww = 0; ww < NWARP; ww++) s += sm[OFF_PART + ww * PSTRIDE + tid];
        s *= L2E;
        const uint32_t pa = sb + (uint32_t)(OFF_PSQ + q * PPC + tid) * 4;
        #pragma unroll
        for (uint32_t rk = 0; rk < CSZ; rk++) st_cluster_pre(mapa_u32(pa, rk), s);
    }
    cluster_arrive();
    cluster_wait();

    const uint32_t comb_b = sb + OFF_COMB * 4;
    const uint32_t kt_b   = sb + OFF_KT * 4;

    float cc = 0.0f;  // persistent cell state (this thread's unit)
    float hh = 0.0f;

    // fixed per-thread roles
    const int r3 = tid >> 6;            // phase-3 row 0..7
    const int u3 = tid & 63;            // phase-3 hidden unit 0..63
    const int qt = w >> 2;              // phase-2 K-quarter 0..3
    const int cp = ((w & 3) << 5) + l;  // phase-2 column pair 0..127
    const int c2 = 2 * cp;              // first column of the pair

    // hoisted DSMEM addresses (loop-invariant mapa)
    uint32_t ka[CSZ], ha[CSZ];
    {
        // finalize role (warps 0-7): proto pf = l, row rf = w
        const int pg = q * PPC + l;
        const uint32_t kaddr = kt_b + (uint32_t)(pg * KTSTR + (w & 7)) * 4;
        const uint32_t haddr = comb_b + (uint32_t)(r3 * CSTR + DIN + q * 64 + u3) * 4;
        #pragma unroll
        for (uint32_t rk = 0; rk < CSZ; rk++) {
            ka[rk] = mapa_u32(kaddr, rk);
            ha[rk] = mapa_u32(haddr, rk);
        }
    }

    // phase-2 fixed addresses
    const uint32_t kb2 = kt_b + (uint32_t)qt * (32 * 48);          // k base for quarter
    const uint32_t wb2 = sb + (uint32_t)(OFF_W + qt * 32 * NCOL + c2) * 4;
    // GP region addresses (u64 granularity, stride 9 per colpair)
    const uint32_t gp_self = sb + OFF_GP * 4 + (uint32_t)(((qt - 1) * GPQ_U64 + cp * 9) * 8);
    const uint32_t gp_rd0  = sb + OFF_GP * 4 + (uint32_t)((cp * 9) * 8);

    // output pointer (bumped per step)
    float* outp = out + ((size_t)(row0 + r3) * HID + q * 64 + u3);

    for (int t = 0; t < TSTEPS; t++) {
        // ---------- phase 1a (warps 8-15): |c|^2 per row ----------
        if (w >= 8) {
            const int r = w - 8;
            const uint32_t a = comb_b + (uint32_t)(r * CSTR * 4) + (uint32_t)l * 16;
            ull a0 = 0, a1 = 0;
            #pragma unroll
            for (int ch = 0; ch < 3; ch++) {
                ull c01, c23;
                lds_v2u64(c01, c23, a + ch * 512);
                a0 = ffma2(c01, c01, a0);
                a1 = ffma2(c23, c23, a1);
            }
            float lo, hi;
            unpack2(lo, hi, fadd2(a0, a1));
            float s = lo + hi;
            s += __shfl_xor_sync(0xFFFFFFFFu, s, 16);
            s += __shfl_xor_sync(0xFFFFFFFFu, s, 8);
            s += __shfl_xor_sync(0xFFFFFFFFu, s, 4);
            s += __shfl_xor_sync(0xFFFFFFFFu, s, 2);
            s += __shfl_xor_sync(0xFFFFFFFFu, s, 1);
            if (l == 0) sm[OFF_CSQ + r] = s;
        }

        // ---------- phase 1b: dot products c.p (16-way split-K, protos in regs) ----------
        {
            const uint32_t cslice = comb_b + w * (DPW * 4);  // this warp's 24-dim slice
            #pragma unroll 1
            for (int r = 0; r < RPC; r++) {
                ull a0 = 0, a1 = 0;
                const uint32_t a = cslice + r * (CSTR * 4);
                #pragma unroll
                for (int jv = 0; jv < 6; jv++) {
                    ull c01, c23;
                    lds_v2u64(c01, c23, a + jv * 16);        // broadcast across warp
                    a0 = ffma2(pr[2 * jv],     c01, a0);
                    a1 = ffma2(pr[2 * jv + 1], c23, a1);
                }
                float lo, hi;
                unpack2(lo, hi, fadd2(a0, a1));
                sm[OFF_PART + w * PSTRIDE + r * 32 + l] = lo + hi;  // conflict-free
            }
        }
        __syncthreads();

        // ---------- prefetch x_{t+1} (consumed in phase 3) ----------
        float2 xv;
        {
            const int tn = (t + 1 < TSTEPS) ? t + 1 : t;
            xv = *(const float2*)&x[((size_t)tn * BATCH + row0 + r3) * DIN + 2 * u3];
        }

        // ---------- finalize k = exp(2*dot - |c|^2 - |p|^2), DSMEM to all CTAs ----------
        if (w < 8) {
            const int pf = l;          // local proto 0..31 (lane)
            const int rf = w;          // row 0..7
            float s0 = 0.0f, s1 = 0.0f;
            #pragma unroll
            for (int s = 0; s < 16; s += 2) {
                s0 += sm[OFF_PART + s * PSTRIDE + rf * 32 + pf];
                s1 += sm[OFF_PART + (s + 1) * PSTRIDE + rf * 32 + pf];
            }
            const float dot = s0 + s1;
            const float t1 = fmaf(L2E, sm[OFF_CSQ + rf], sm[OFF_PSQ + q * PPC + pf]);
            const float kv = fex2(fmaf(2.0f * L2E, dot, -t1));
            #pragma unroll
            for (uint32_t rk = 0; rk < CSZ; rk++) st_cluster_pre(ka[rk], kv);
        }
        __syncthreads();  // local kt quarter fully written

        cluster_arrive();

        // ---------- phase 2: gate GEMM (2 cols/thread, quarter-K, 4-way reduce) ----------
        // accumulators: col c2 rows (0,1)(2,3)(4,5)(6,7); col c2+1 same
        ull ac0 = 0, ac1 = 0, ac2 = 0, ac3 = 0;
        ull ad0 = 0, ad1 = 0, ad2 = 0, ad3 = 0;

        #define GEMM_QUARTER()                                                    \
        {                                                                         \
            _Pragma("unroll 8")                                                   \
            for (int p = 0; p < 32; p++) {                                        \
                ull k01, k23, k45, k67;                                           \
                lds_v2u64(k01, k23, kb2 + p * 48);                                \
                lds_v2u64(k45, k67, kb2 + p * 48 + 16);                           \
                float w0, w1;                                                     \
                lds_v2f32(w0, w1, wb2 + (uint32_t)p * (NCOL * 4));                \
                const ull ww0 = splat2(w0);                                       \
                const ull ww1 = splat2(w1);                                       \
                ac0 = ffma2(k01, ww0, ac0);                                       \
                ac1 = ffma2(k23, ww0, ac1);                                       \
                ac2 = ffma2(k45, ww0, ac2);                                       \
                ac3 = ffma2(k67, ww0, ac3);                                       \
                ad0 = ffma2(k01, ww1, ad0);                                       \
                ad1 = ffma2(k23, ww1, ad1);                                       \
                ad2 = ffma2(k45, ww1, ad2);                                       \
                ad3 = ffma2(k67, ww1, ad3);                                       \
            }                                                                     \
            if (qt) {                                                             \
                sts_u64(gp_self,      ac0);                                       \
                sts_u64(gp_self + 8,  ac1);                                       \
                sts_u64(gp_self + 16, ac2);                                       \
                sts_u64(gp_self + 24, ac3);                                       \
                sts_u64(gp_self + 32, ad0);                                       \
                sts_u64(gp_self + 40, ad1);                                       \
                sts_u64(gp_self + 48, ad2);                                       \
                sts_u64(gp_self + 56, ad3);                                       \
            }                                                                     \
        }

        // Warps whose quarter == own rank need only locally-produced k rows:
        // run them between arrive and wait to hide cluster latency.
        if (qt == (int)q) GEMM_QUARTER();
        cluster_wait();   // sync #1: full k in every CTA
        if (qt != (int)q) GEMM_QUARTER();
        __syncthreads();

        if (!qt) {  // quarter 0 reduces + bias + writes G
            #pragma unroll
            for (int qq = 0; qq < 3; qq++) {
                const uint32_t b = gp_rd0 + (uint32_t)(qq * GPQ_U64 * 8);
                ac0 = fadd2(ac0, lds_u64(b));
                ac1 = fadd2(ac1, lds_u64(b + 8));
                ac2 = fadd2(ac2, lds_u64(b + 16));
                ac3 = fadd2(ac3, lds_u64(b + 24));
                ad0 = fadd2(ad0, lds_u64(b + 32));
                ad1 = fadd2(ad1, lds_u64(b + 40));
                ad2 = fadd2(ad2, lds_u64(b + 48));
                ad3 = fadd2(ad3, lds_u64(b + 56));
            }
            float bx, by;
            lds_v2f32(bx, by, sb + (uint32_t)(OFF_B + c2) * 4);
            const ull bbx = splat2(bx), bby = splat2(by);
            ac0 = fadd2(ac0, bbx); ac1 = fadd2(ac1, bbx);
            ac2 = fadd2(ac2, bbx); ac3 = fadd2(ac3, bbx);
            ad0 = fadd2(ad0, bby); ad1 = fadd2(ad1, bby);
            ad2 = fadd2(ad2, bby); ad3 = fadd2(ad3, bby);
            float v0, v1;
            unpack2(v0, v1, ac0);
            sm[OFF_G + 0 * GSTR + c2] = v0; sm[OFF_G + 1 * GSTR + c2] = v1;
            unpack2(v0, v1, ac1);
            sm[OFF_G + 2 * GSTR + c2] = v0; sm[OFF_G + 3 * GSTR + c2] = v1;
            unpack2(v0, v1, ac2);
            sm[OFF_G + 4 * GSTR + c2] = v0; sm[OFF_G + 5 * GSTR + c2] = v1;
            unpack2(v0, v1, ac3);
            sm[OFF_G + 6 * GSTR + c2] = v0; sm[OFF_G + 7 * GSTR + c2] = v1;
            unpack2(v0, v1, ad0);
            sm[OFF_G + 0 * GSTR + c2 + 1] = v0; sm[OFF_G + 1 * GSTR + c2 + 1] = v1;
            unpack2(v0, v1, ad1);
            sm[OFF_G + 2 * GSTR + c2 + 1] = v0; sm[OFF_G + 3 * GSTR + c2 + 1] = v1;
            unpack2(v0, v1, ad2);
            sm[OFF_G + 4 * GSTR + c2 + 1] = v0; sm[OFF_G + 5 * GSTR + c2 + 1] = v1;
            unpack2(v0, v1, ad3);
            sm[OFF_G + 6 * GSTR + c2 + 1] = v0; sm[OFF_G + 7 * GSTR + c2 + 1] = v1;
        }
        __syncthreads();

        // ---------- phase 3: LSTM update (1 unit/thread), h broadcast, x install ----------
        {
            const float* gr = &sm[OFF_G + r3 * GSTR + u3];
            const float gf = gr[0];
            const float gi = gr[64];
            const float gg = gr[128];
            const float go = gr[192];
            const float fv = fsigm(gf);
            const float iv = fsigm(gi);
            const float gv = ftanh(gg);
            const float ov = fsigm(go);
            cc = fv * cc + iv * gv;
            const float h = ov * ftanh(cc);
            hh = h;
            *outp = h;
            outp += (size_t)BATCH * HID;
            #pragma unroll
            for (uint32_t rk = 0; rk < CSZ; rk++) st_cluster_pre(ha[rk], h);
        }
        cluster_arrive();
        // install prefetched x_{t+1} (local-only region of comb) under cluster latency
        *(float2*)&sm[OFF_COMB + r3 * CSTR + 2 * u3] = xv;
        cluster_wait();   // sync #2: comb (x, h) ready for next step
    }

    // ---------------- epilogue: hx, cx ----------------
    {
        const size_t base = (size_t)TSTEPS * BATCH * HID;
        if ((size_t)out_size >= base + 2 * (size_t)BATCH * HID) {
            const size_t idx = (size_t)(row0 + r3) * HID + q * 64 + u3;
            out[base + idx] = hh;
            out[base + (size_t)BATCH * HID + idx] = cc;
        }
    }
}

// ---------------- launch ----------------
extern "C" void kernel_launch(void* const* d_in, const int* in_sizes, int n_in,
                              void* d_out, int out_size) {
    const float* x      = (const float*)d_in[0];
    const float* protos = (const float*)d_in[1];
    const float* Wf     = (const float*)d_in[2];
    const float* bf     = (const float*)d_in[3];
    const float* Wi     = (const float*)d_in[4];
    const float* bi     = (const float*)d_in[5];
    const float* Wg     = (const float*)d_in[6];
    const float* bg     = (const float*)d_in[7];
    const float* Wo     = (const float*)d_in[8];
    const float* bo     = (const float*)d_in[9];

    cudaFuncSetAttribute(qlstm_kernel,
                         cudaFuncAttributeMaxDynamicSharedMemorySize, SMEM_BYTES);

    qlstm_kernel<<<NCLUST * CSZ, NTHR, SMEM_BYTES>>>(
        x, protos, Wf, bf, Wi, bi, Wg, bg, Wo, bo,
        (float*)d_out, out_size);
}